// round 1
// baseline (speedup 1.0000x reference)
#include <cuda_runtime.h>

// Problem constants (fixed by setup_inputs)
#define BATCH 64
#define NGT   1024
#define MPRED 2048
#define THRESH2 256.0f   // 16.0^2

// Scratch: per-(batch, gt) minimum matched pred index. INT_MAX sentinel.
__device__ int g_best[BATCH * NGT];

__global__ void init_best_kernel() {
    int i = blockIdx.x * blockDim.x + threadIdx.x;
    if (i < BATCH * NGT) g_best[i] = 0x7FFFFFFF;
}

// One thread = one pred. Grid = BATCH * (MPRED / blockDim.x).
// GT tile for the batch staged in shared; warp-uniform index -> broadcast LDS.
__global__ __launch_bounds__(256) void match_kernel(
    const float2* __restrict__ gt,    // [BATCH, NGT]
    const float2* __restrict__ pred)  // [BATCH, MPRED]
{
    const int PARTS = MPRED / 256;               // 8 partitions of preds
    const int b    = blockIdx.x / PARTS;
    const int part = blockIdx.x % PARTS;

    __shared__ float2 sgt[NGT];
    for (int i = threadIdx.x; i < NGT; i += blockDim.x)
        sgt[i] = gt[b * NGT + i];
    __syncthreads();

    const int j = part * 256 + threadIdx.x;      // pred index within batch
    const float2 p = pred[b * MPRED + j];

    float best = 3.402823e38f;
    int   bi   = 0;

    // Ascending i + strict < reproduces jnp.argmin first-occurrence tie rule.
    // __fmul_rn/__fadd_rn forbid FMA contraction -> bit-match reference d2.
    #pragma unroll 8
    for (int i = 0; i < NGT; i++) {
        float2 g = sgt[i];
        float dx = p.x - g.x;
        float dy = p.y - g.y;
        float d2 = __fadd_rn(__fmul_rn(dx, dx), __fmul_rn(dy, dy));
        if (d2 < best) { best = d2; bi = i; }
    }

    if (best < THRESH2)
        atomicMin(&g_best[b * NGT + bi], j);
}

__global__ void gather_kernel(
    const float2* __restrict__ gt,
    const float2* __restrict__ pred,
    float2* __restrict__ out)
{
    int idx = blockIdx.x * blockDim.x + threadIdx.x;
    if (idx >= BATCH * NGT) return;
    int b = idx / NGT;
    int j = g_best[idx];
    out[idx] = (j < MPRED) ? pred[b * MPRED + j] : gt[idx];
}

extern "C" void kernel_launch(void* const* d_in, const int* in_sizes, int n_in,
                              void* d_out, int out_size) {
    const float2* gt   = (const float2*)d_in[0];   // gt_locations   [64,1024,2] f32
    const float2* pred = (const float2*)d_in[1];   // pred_locations [64,2048,2] f32
    float2* out = (float2*)d_out;                  // [64,1024,2] f32

    init_best_kernel<<<(BATCH * NGT + 511) / 512, 512>>>();
    match_kernel<<<BATCH * (MPRED / 256), 256>>>(gt, pred);
    gather_kernel<<<(BATCH * NGT + 255) / 256, 256>>>(gt, pred, out);
}

// round 2
// speedup vs baseline: 1.1293x; 1.1293x over previous
#include <cuda_runtime.h>
#include <cstdint>

// Problem constants (fixed by setup_inputs)
#define BATCH 64
#define NGT   1024
#define MPRED 2048
#define THRESH2 256.0f   // 16.0^2

// Scratch: per-(batch, gt) stores max over matching preds of (MPRED - j),
// i.e. MPRED - min_j. Sentinel 0 = unmatched. Zero-initialized at module
// load; gather_kernel resets to 0 after each read, so every launch sees
// all-zero scratch (graph-replay safe, no init kernel needed).
__device__ int g_best[BATCH * NGT];

// 2 preds per thread, both packed in f32x2 lanes. GT tile staged in shared
// pre-negated and lane-duplicated: {-gx,-gx,-gy,-gy} per gt -> one broadcast
// LDS.128 per iteration, zero packing MOVs, and add.rn.f32x2 computes
// dx = p + (-g) with per-lane rn (bit-identical to scalar sub).
__global__ __launch_bounds__(128) void match_kernel(
    const float2* __restrict__ gt,    // [BATCH, NGT]
    const float2* __restrict__ pred)  // [BATCH, MPRED]
{
    const int PARTS = MPRED / 256;               // 8 partitions of 256 preds
    const int b    = blockIdx.x >> 3;
    const int part = blockIdx.x & 7;

    __shared__ ulonglong2 sgt[NGT];              // {(-gx,-gx),(-gy,-gy)} packed

    for (int i = threadIdx.x; i < NGT; i += 128) {
        float2 g = gt[b * NGT + i];
        float2 nx = make_float2(-g.x, -g.x);
        float2 ny = make_float2(-g.y, -g.y);
        ulonglong2 v;
        v.x = *reinterpret_cast<unsigned long long*>(&nx);
        v.y = *reinterpret_cast<unsigned long long*>(&ny);
        sgt[i] = v;
    }
    __syncthreads();

    const int j0 = part * 256 + threadIdx.x;     // pred indices for this thread
    const int j1 = j0 + 128;
    const float2 p0 = pred[b * MPRED + j0];
    const float2 p1 = pred[b * MPRED + j1];

    float2 pxv = make_float2(p0.x, p1.x);
    float2 pyv = make_float2(p0.y, p1.y);
    const unsigned long long px2 = *reinterpret_cast<unsigned long long*>(&pxv);
    const unsigned long long py2 = *reinterpret_cast<unsigned long long*>(&pyv);

    // best initialized to THRESH2: strict < makes selection double as the
    // threshold test. bi<0 <=> unmatched. First-occurrence tie rule of
    // jnp.argmin preserved (ascending i, strict <).
    float best0 = THRESH2, best1 = THRESH2;
    int   bi0 = -1, bi1 = -1;

    #pragma unroll 4
    for (int i = 0; i < NGT; i++) {
        ulonglong2 g = sgt[i];                   // LDS.128 broadcast
        unsigned long long dx2, dy2, xx, yy, d2;
        asm("add.rn.f32x2 %0, %1, %2;" : "=l"(dx2) : "l"(px2), "l"(g.x));
        asm("add.rn.f32x2 %0, %1, %2;" : "=l"(dy2) : "l"(py2), "l"(g.y));
        asm("mul.rn.f32x2 %0, %1, %1;" : "=l"(xx) : "l"(dx2));
        asm("mul.rn.f32x2 %0, %1, %1;" : "=l"(yy) : "l"(dy2));
        asm("add.rn.f32x2 %0, %1, %2;" : "=l"(d2) : "l"(xx), "l"(yy));
        float d0 = __uint_as_float((unsigned int)d2);
        float d1 = __uint_as_float((unsigned int)(d2 >> 32));
        if (d0 < best0) { best0 = d0; bi0 = i; }
        if (d1 < best1) { best1 = d1; bi1 = i; }
    }

    if (bi0 >= 0) atomicMax(&g_best[b * NGT + bi0], MPRED - j0);
    if (bi1 >= 0) atomicMax(&g_best[b * NGT + bi1], MPRED - j1);
}

__global__ void gather_kernel(
    const float2* __restrict__ gt,
    const float2* __restrict__ pred,
    float2* __restrict__ out)
{
    int idx = blockIdx.x * blockDim.x + threadIdx.x;
    if (idx >= BATCH * NGT) return;
    int b = idx >> 10;
    int s = g_best[idx];                     // MPRED - jmin, or 0 = unmatched
    float2 r;
    if (s > 0) r = pred[b * MPRED + (MPRED - s)];
    else       r = gt[idx];
    out[idx] = r;
    g_best[idx] = 0;                         // reset invariant for next launch
}

extern "C" void kernel_launch(void* const* d_in, const int* in_sizes, int n_in,
                              void* d_out, int out_size) {
    const float2* gt   = (const float2*)d_in[0];   // gt_locations   [64,1024,2] f32
    const float2* pred = (const float2*)d_in[1];   // pred_locations [64,2048,2] f32
    float2* out = (float2*)d_out;                  // [64,1024,2] f32

    match_kernel<<<BATCH * (MPRED / 256), 128>>>(gt, pred);
    gather_kernel<<<(BATCH * NGT + 255) / 256, 256>>>(gt, pred, out);
}

// round 3
// speedup vs baseline: 1.1838x; 1.0483x over previous
#include <cuda_runtime.h>
#include <cstdint>

// Problem constants (fixed by setup_inputs)
#define BATCH 64
#define NGT   1024
#define MPRED 2048
#define THRESH2 256.0f   // 16.0^2

// Scratch: per-(batch, gt) stores max over matching preds of (MPRED - j),
// i.e. MPRED - min_j. Sentinel 0 = unmatched. Zero-initialized at module
// load; gather_kernel resets to 0 after each read, so every launch sees
// all-zero scratch (graph-replay safe, no init kernel needed).
__device__ int g_best[BATCH * NGT];

// 2 preds per thread packed in f32x2 lanes. GT tile staged in shared
// pre-negated and lane-duplicated: {-gx,-gx,-gy,-gy} -> one broadcast
// LDS.128 per iteration; add.rn.f32x2 computes dx = p + (-g), per-lane rn,
// bit-identical to scalar sub.
//
// Selection is BRANCHLESS (ternaries -> FSETP + SEL/FSEL). The R2 version
// used if{} which ptxas wraps in BSSY/BSYNC (33-56 cyc each) -- that was
// ~70% overhead on the inner loop.
__global__ __launch_bounds__(128) void match_kernel(
    const float2* __restrict__ gt,    // [BATCH, NGT]
    const float2* __restrict__ pred)  // [BATCH, MPRED]
{
    const int b    = blockIdx.x >> 3;
    const int part = blockIdx.x & 7;

    __shared__ ulonglong2 sgt[NGT];              // {(-gx,-gx),(-gy,-gy)}

    for (int i = threadIdx.x; i < NGT; i += 128) {
        float2 g = gt[b * NGT + i];
        float2 nx = make_float2(-g.x, -g.x);
        float2 ny = make_float2(-g.y, -g.y);
        ulonglong2 v;
        v.x = *reinterpret_cast<unsigned long long*>(&nx);
        v.y = *reinterpret_cast<unsigned long long*>(&ny);
        sgt[i] = v;
    }
    __syncthreads();

    const int j0 = part * 256 + threadIdx.x;
    const int j1 = j0 + 128;
    const float2 p0 = pred[b * MPRED + j0];
    const float2 p1 = pred[b * MPRED + j1];

    float2 pxv = make_float2(p0.x, p1.x);
    float2 pyv = make_float2(p0.y, p1.y);
    const unsigned long long px2 = *reinterpret_cast<const unsigned long long*>(&pxv);
    const unsigned long long py2 = *reinterpret_cast<const unsigned long long*>(&pyv);

    // best starts at THRESH2: strict < doubles as the threshold test.
    // bi<0 <=> unmatched. Ascending i + strict < = jnp.argmin first-min rule.
    float best0 = THRESH2, best1 = THRESH2;
    int   bi0 = -1, bi1 = -1;

    #pragma unroll 8
    for (int i = 0; i < NGT; i++) {
        ulonglong2 g = sgt[i];                   // LDS.128 broadcast
        unsigned long long dx2, dy2, xx, yy, d2;
        asm("add.rn.f32x2 %0, %1, %2;" : "=l"(dx2) : "l"(px2), "l"(g.x));
        asm("add.rn.f32x2 %0, %1, %2;" : "=l"(dy2) : "l"(py2), "l"(g.y));
        asm("mul.rn.f32x2 %0, %1, %1;" : "=l"(xx) : "l"(dx2));
        asm("mul.rn.f32x2 %0, %1, %1;" : "=l"(yy) : "l"(dy2));
        asm("add.rn.f32x2 %0, %1, %2;" : "=l"(d2) : "l"(xx), "l"(yy));
        float d0 = __uint_as_float((unsigned int)d2);
        float d1 = __uint_as_float((unsigned int)(d2 >> 32));
        // branchless: FSETP + SEL + FSEL, no BSSY/BSYNC
        bool c0 = d0 < best0;
        bool c1 = d1 < best1;
        bi0   = c0 ? i  : bi0;
        best0 = c0 ? d0 : best0;
        bi1   = c1 ? i  : bi1;
        best1 = c1 ? d1 : best1;
    }

    if (bi0 >= 0) atomicMax(&g_best[b * NGT + bi0], MPRED - j0);
    if (bi1 >= 0) atomicMax(&g_best[b * NGT + bi1], MPRED - j1);
}

__global__ void gather_kernel(
    const float2* __restrict__ gt,
    const float2* __restrict__ pred,
    float2* __restrict__ out)
{
    int idx = blockIdx.x * blockDim.x + threadIdx.x;
    if (idx >= BATCH * NGT) return;
    int b = idx >> 10;
    int s = g_best[idx];                     // MPRED - jmin, or 0 = unmatched
    float2 r;
    if (s > 0) r = pred[b * MPRED + (MPRED - s)];
    else       r = gt[idx];
    out[idx] = r;
    g_best[idx] = 0;                         // reset invariant for next launch
}

extern "C" void kernel_launch(void* const* d_in, const int* in_sizes, int n_in,
                              void* d_out, int out_size) {
    const float2* gt   = (const float2*)d_in[0];   // [64,1024,2] f32
    const float2* pred = (const float2*)d_in[1];   // [64,2048,2] f32
    float2* out = (float2*)d_out;                  // [64,1024,2] f32

    match_kernel<<<BATCH * (MPRED / 256), 128>>>(gt, pred);
    gather_kernel<<<(BATCH * NGT + 255) / 256, 256>>>(gt, pred, out);
}

// round 4
// speedup vs baseline: 4.3212x; 3.6503x over previous
#include <cuda_runtime.h>

#define BATCH   64
#define NGT     1024
#define MPRED   2048
#define THRESH2 256.0f    // 16.0^2
#define GDIM    32        // 32x32 grid of 16px cells (512 / 16)
#define NCELL   (GDIM * GDIM)

// One block per batch. Phase 1: bin the 1024 gts into a 32x32 cell grid in
// shared (CSR: exclusive offsets + coords + original index). Phase 2: each
// thread resolves 2 preds by scanning the 3x3 cell neighborhood (3 contiguous
// runs). A pred's match only matters if min d2 < 256 (= within 16px), and any
// gt within 16px of a pred lies in the 3x3 neighborhood of the pred's cell,
// so this is EXACTLY equivalent to the full argmin:
//   - if neighborhood min < 256, it equals the global min and the global
//     argmin gt is in the neighborhood;
//   - if neighborhood has nothing < 256, the global min >= 256 -> unmatched.
// d2 uses __fadd_rn/__fmul_rn (no FMA contraction) -> bit-identical to the
// reference mul-then-add. Tie rule (d2 == best -> lowest gt index) is applied
// explicitly, so scan order inside cells is irrelevant.
// Phase 3: per-gt min pred index via SHARED-memory atomicMin, then the gather
// is fused in-block. No global scratch, single launch.
__global__ __launch_bounds__(1024, 1) void lacss_match_kernel(
    const float2* __restrict__ gt,    // [BATCH, NGT]
    const float2* __restrict__ pred,  // [BATCH, MPRED]
    float2* __restrict__ out)         // [BATCH, NGT]
{
    __shared__ int    s_cnt[NCELL];      // counts, then scatter cursor
    __shared__ int    s_off[NCELL + 1];  // exclusive CSR offsets
    __shared__ float2 s_gt[NGT];         // gt coords in binned order
    __shared__ int    s_idx[NGT];        // original gt index
    __shared__ int    s_best[NGT];       // min matched pred j per gt
    __shared__ int    s_wsum[32];

    const int b    = blockIdx.x;
    const int tid  = threadIdx.x;
    const int lane = tid & 31;
    const int wid  = tid >> 5;

    // ---- load my gt, compute its cell (x*2^-4 is exact, coords in [0,512)) ----
    const float2 g = gt[b * NGT + tid];
    const int gcell = (int)(g.y * 0.0625f) * GDIM + (int)(g.x * 0.0625f);

    s_cnt[tid]  = 0;
    s_best[tid] = MPRED;                 // sentinel: unmatched
    __syncthreads();

    atomicAdd(&s_cnt[gcell], 1);
    __syncthreads();

    // ---- exclusive prefix sum of s_cnt -> s_off (1024 elems, 32 warps) ----
    int v   = s_cnt[tid];
    int inc = v;
    #pragma unroll
    for (int d = 1; d < 32; d <<= 1) {
        int n = __shfl_up_sync(0xFFFFFFFFu, inc, d);
        if (lane >= d) inc += n;
    }
    if (lane == 31) s_wsum[wid] = inc;
    __syncthreads();
    if (wid == 0) {
        int w  = s_wsum[lane];
        int wi = w;
        #pragma unroll
        for (int d = 1; d < 32; d <<= 1) {
            int n = __shfl_up_sync(0xFFFFFFFFu, wi, d);
            if (lane >= d) wi += n;
        }
        s_wsum[lane] = wi - w;           // exclusive offset of warp `lane`
    }
    __syncthreads();
    s_off[tid] = (inc - v) + s_wsum[wid];
    if (tid == 0) s_off[NCELL] = NGT;
    __syncthreads();

    s_cnt[tid] = s_off[tid];             // cursor = copy of offsets
    __syncthreads();

    // ---- scatter gts into binned order ----
    {
        int pos = atomicAdd(&s_cnt[gcell], 1);
        s_gt[pos]  = g;
        s_idx[pos] = tid;
    }
    __syncthreads();

    // ---- pred phase: 2 preds per thread, scan 3x3 neighborhood ----
    #pragma unroll
    for (int r = 0; r < 2; r++) {
        const int j = r * 1024 + tid;
        const float2 p = pred[b * MPRED + j];
        const int pcx = (int)(p.x * 0.0625f);
        const int pcy = (int)(p.y * 0.0625f);
        const int x0 = max(pcx - 1, 0), x1 = min(pcx + 1, GDIM - 1);
        const int y0 = max(pcy - 1, 0), y1 = min(pcy + 1, GDIM - 1);

        float best = THRESH2;            // strict < doubles as threshold test
        int   bi   = -1;

        for (int cy = y0; cy <= y1; cy++) {
            const int ks = s_off[cy * GDIM + x0];
            const int ke = s_off[cy * GDIM + x1 + 1];   // cells contiguous in x
            for (int k = ks; k < ke; k++) {
                float2 q = s_gt[k];
                int   gi = s_idx[k];
                float dx = __fadd_rn(p.x, -q.x);
                float dy = __fadd_rn(p.y, -q.y);
                float d2 = __fadd_rn(__fmul_rn(dx, dx), __fmul_rn(dy, dy));
                // first-index argmin tie rule, order-independent
                bool take = (d2 < best) || (d2 == best && gi < bi);
                bi   = take ? gi : bi;
                best = take ? d2 : best;
            }
        }
        if (bi >= 0) atomicMin(&s_best[bi], j);
    }
    __syncthreads();

    // ---- fused gather: out[b, tid] ----
    const int s = s_best[tid];
    out[b * NGT + tid] = (s < MPRED) ? pred[b * MPRED + s] : g;
}

extern "C" void kernel_launch(void* const* d_in, const int* in_sizes, int n_in,
                              void* d_out, int out_size) {
    const float2* gt   = (const float2*)d_in[0];   // gt_locations   [64,1024,2] f32
    const float2* pred = (const float2*)d_in[1];   // pred_locations [64,2048,2] f32
    float2* out = (float2*)d_out;                  // [64,1024,2] f32

    lacss_match_kernel<<<BATCH, 1024>>>(gt, pred, out);
}

// round 5
// speedup vs baseline: 4.8772x; 1.1287x over previous
#include <cuda_runtime.h>
#include <cooperative_groups.h>

namespace cg = cooperative_groups;

#define BATCH   64
#define NGT     1024
#define MPRED   2048
#define THRESH2 256.0f    // 16.0^2
#define GDIM    32        // 32x32 grid of 16px cells (512 / 16)
#define NCELL   (GDIM * GDIM)

// Cluster of 2 CTAs per batch (grid=128). Each CTA independently bins the
// batch's 1024 gts into a 32x32 cell CSR in its own shared memory (binning is
// cheap; duplicating it keeps the hot scan loop on 29-cycle LDS instead of
// 215-cycle DSMEM). Each CTA then scans 1024 preds (rank r -> preds
// [r*1024, r*1024+1024)) against the 3x3 cell neighborhood — exactly
// equivalent to the full argmin because matches only matter under the 16px
// threshold, and any gt within 16px lies in the 3x3 neighborhood.
// Both CTAs atomicMin their (gt -> min pred index) updates into RANK 0's
// s_best via distributed shared memory; cluster.sync() orders them; rank 0
// does the fused gather. One launch, no global scratch.
// d2 uses __fadd_rn/__fmul_rn (no FMA) -> bit-identical to reference.
// Tie rule (equal d2 -> lower gt index) applied explicitly, so scatter and
// atomic ordering are irrelevant to the result.
__global__ __launch_bounds__(1024, 1) __cluster_dims__(2, 1, 1)
void lacss_match_kernel(
    const float2* __restrict__ gt,    // [BATCH, NGT]
    const float2* __restrict__ pred,  // [BATCH, MPRED]
    float2* __restrict__ out)         // [BATCH, NGT]
{
    __shared__ int    s_cnt[NCELL];      // counts, then scatter cursor
    __shared__ int    s_off[NCELL + 1];  // exclusive CSR offsets
    __shared__ float2 s_gt[NGT];         // gt coords in binned order
    __shared__ int    s_idx[NGT];        // original gt index
    __shared__ int    s_best[NGT];       // min matched pred j per gt (rank0's is authoritative)
    __shared__ int    s_wsum[32];

    cg::cluster_group cluster = cg::this_cluster();
    const unsigned rank = cluster.block_rank();

    const int b    = blockIdx.x >> 1;
    const int tid  = threadIdx.x;
    const int lane = tid & 31;
    const int wid  = tid >> 5;

    // ---- load my gt, compute its cell (x * 2^-4 is exact) ----
    const float2 g = gt[b * NGT + tid];
    const int gcell = (int)(g.y * 0.0625f) * GDIM + (int)(g.x * 0.0625f);

    s_cnt[tid]  = 0;
    s_best[tid] = MPRED;                 // sentinel: unmatched
    __syncthreads();

    atomicAdd(&s_cnt[gcell], 1);
    __syncthreads();

    // ---- exclusive prefix sum of s_cnt -> s_off ----
    int v   = s_cnt[tid];
    int inc = v;
    #pragma unroll
    for (int d = 1; d < 32; d <<= 1) {
        int n = __shfl_up_sync(0xFFFFFFFFu, inc, d);
        if (lane >= d) inc += n;
    }
    if (lane == 31) s_wsum[wid] = inc;
    __syncthreads();
    if (wid == 0) {
        int w  = s_wsum[lane];
        int wi = w;
        #pragma unroll
        for (int d = 1; d < 32; d <<= 1) {
            int n = __shfl_up_sync(0xFFFFFFFFu, wi, d);
            if (lane >= d) wi += n;
        }
        s_wsum[lane] = wi - w;           // exclusive offset of warp `lane`
    }
    __syncthreads();
    s_off[tid] = (inc - v) + s_wsum[wid];
    if (tid == 0) s_off[NCELL] = NGT;
    __syncthreads();

    s_cnt[tid] = s_off[tid];             // cursor = copy of offsets
    __syncthreads();

    // ---- scatter gts into binned order ----
    {
        int pos = atomicAdd(&s_cnt[gcell], 1);
        s_gt[pos]  = g;
        s_idx[pos] = tid;
    }
    __syncthreads();

    // ---- pred phase: ONE pred per thread (rank splits the 2048) ----
    {
        const int j = (int)rank * 1024 + tid;
        const float2 p = pred[b * MPRED + j];
        const int pcx = (int)(p.x * 0.0625f);
        const int pcy = (int)(p.y * 0.0625f);
        const int x0 = max(pcx - 1, 0), x1 = min(pcx + 1, GDIM - 1);
        const int y0 = max(pcy - 1, 0), y1 = min(pcy + 1, GDIM - 1);

        float best = THRESH2;            // strict < doubles as threshold test
        int   bi   = -1;

        for (int cy = y0; cy <= y1; cy++) {
            const int ks = s_off[cy * GDIM + x0];
            const int ke = s_off[cy * GDIM + x1 + 1];   // cells contiguous in x
            for (int k = ks; k < ke; k++) {
                float2 q = s_gt[k];
                int   gi = s_idx[k];
                float dx = __fadd_rn(p.x, -q.x);
                float dy = __fadd_rn(p.y, -q.y);
                float d2 = __fadd_rn(__fmul_rn(dx, dx), __fmul_rn(dy, dy));
                bool take = (d2 < best) || (d2 == best && gi < bi);
                bi   = take ? gi : bi;
                best = take ? d2 : best;
            }
        }

        if (bi >= 0) {
            // merge into rank0's s_best (local smem atomic for rank0,
            // DSMEM atomic for rank1)
            int* dst = (rank == 0) ? s_best
                                   : cluster.map_shared_rank(s_best, 0);
            atomicMin(&dst[bi], j);
        }
    }

    cluster.sync();                      // orders remote atomics before gather

    // ---- fused gather by rank 0 ----
    if (rank == 0) {
        const int s = s_best[tid];
        out[b * NGT + tid] = (s < MPRED) ? pred[b * MPRED + s] : g;
    }
}

extern "C" void kernel_launch(void* const* d_in, const int* in_sizes, int n_in,
                              void* d_out, int out_size) {
    const float2* gt   = (const float2*)d_in[0];   // gt_locations   [64,1024,2] f32
    const float2* pred = (const float2*)d_in[1];   // pred_locations [64,2048,2] f32
    float2* out = (float2*)d_out;                  // [64,1024,2] f32

    lacss_match_kernel<<<BATCH * 2, 1024>>>(gt, pred, out);
}